// round 6
// baseline (speedup 1.0000x reference)
#include <cuda_runtime.h>

#define N_NODES 100000
#define HIDDEN  128
#define HID4    (HIDDEN / 4)
#define BN_EPS  1e-5f

// Scratch (device globals: no allocation allowed in kernel_launch).
// Declared as float4 so LDG.128/LDS.128 paths are guaranteed 16B-aligned.
__device__ float4 g_h4[(size_t)N_NODES * HID4];    // relu(x) @ W
__device__ int    g_deg[N_NODES];
__device__ float  g_dinv[N_NODES];
__device__ double g_sum[HIDDEN];
__device__ double g_sumsq[HIDDEN];
__device__ float4 g_scale4[HID4];
__device__ float4 g_shift4[HID4];

// Vector reduction into GLOBAL space. red.add.v4.f32 is only legal in
// .global — generic-space vector atomics trap. Explicitly convert the
// pointer and qualify the address space.
__device__ __forceinline__ void red_add_global_f4(float* addr, float4 v)
{
    unsigned long long gp = (unsigned long long)__cvta_generic_to_global(addr);
    asm volatile("red.global.add.v4.f32 [%0], {%1, %2, %3, %4};"
                 :: "l"(gp), "f"(v.x), "f"(v.y), "f"(v.z), "f"(v.w)
                 : "memory");
}

// ---------------------------------------------------------------------------
// Init: zero output (poisoned by harness), deg=1 (self loops), zero BN accum.
// ---------------------------------------------------------------------------
__global__ void k_init(float* __restrict__ out, int total)
{
    int i = blockIdx.x * blockDim.x + threadIdx.x;
    int stride = gridDim.x * blockDim.x;
    for (int idx = i; idx < total; idx += stride) out[idx] = 0.0f;
    for (int idx = i; idx < N_NODES; idx += stride) g_deg[idx] = 1;
    if (i < HIDDEN) { g_sum[i] = 0.0; g_sumsq[i] = 0.0; }
}

// ---------------------------------------------------------------------------
// Degree of target nodes (col), on top of the self-loop baseline of 1.
// edge_index is int32 (JAX default config downcasts int64 -> int32).
// ---------------------------------------------------------------------------
__global__ void k_deg(const int* __restrict__ col, int E)
{
    int i = blockIdx.x * blockDim.x + threadIdx.x;
    if (i < E) {
        int c = col[i];
        if (c >= 0 && c < N_NODES) atomicAdd(&g_deg[c], 1);
    }
}

__global__ void k_dinv()
{
    int i = blockIdx.x * blockDim.x + threadIdx.x;
    if (i < N_NODES) g_dinv[i] = rsqrtf((float)g_deg[i]);
}

// ---------------------------------------------------------------------------
// h = relu(x) @ W.
// Block: 64 rows x 128 cols, 256 threads. x-tile (64x128 fp32 = 32KB) in
// smem; W read from global (64KB, L1-resident, coalesced broadcast across
// blocks). Each thread: col c, row-group rg, 32 register accumulators.
// ---------------------------------------------------------------------------
#define TILE_M 64

__global__ void __launch_bounds__(256) k_gemm(const float* __restrict__ x,
                                              const float* __restrict__ W)
{
    __shared__ __align__(16) float xs[TILE_M * HIDDEN];   // 32 KB

    const int tid = threadIdx.x;
    const int rowBase = blockIdx.x * TILE_M;

    // Load tile with ReLU applied, vectorized. 64*32 = 2048 float4 total.
    {
        const float4* x4 = (const float4*)x;
        float4* xs4 = (float4*)xs;
        for (int i = tid; i < TILE_M * HID4; i += 256) {
            int row = rowBase + (i >> 5);                 // 32 float4 per row
            float4 v = make_float4(0.f, 0.f, 0.f, 0.f);
            if (row < N_NODES) {
                v = x4[(size_t)row * HID4 + (i & 31)];
                v.x = fmaxf(v.x, 0.f); v.y = fmaxf(v.y, 0.f);
                v.z = fmaxf(v.z, 0.f); v.w = fmaxf(v.w, 0.f);
            }
            xs4[i] = v;
        }
    }
    __syncthreads();

    const int c  = tid & (HIDDEN - 1);
    const int rg = tid >> 7;                              // 0..1 (32 rows each)

    float acc[32];
    #pragma unroll
    for (int r = 0; r < 32; r++) acc[r] = 0.f;

    for (int k4 = 0; k4 < HID4; k4++) {
        const float w0 = __ldg(&W[(k4 * 4 + 0) * HIDDEN + c]);
        const float w1 = __ldg(&W[(k4 * 4 + 1) * HIDDEN + c]);
        const float w2 = __ldg(&W[(k4 * 4 + 2) * HIDDEN + c]);
        const float w3 = __ldg(&W[(k4 * 4 + 3) * HIDDEN + c]);
        #pragma unroll
        for (int r = 0; r < 32; r++) {
            float4 xv = *(const float4*)&xs[(rg * 32 + r) * HIDDEN + k4 * 4];
            acc[r] = fmaf(xv.x, w0, acc[r]);
            acc[r] = fmaf(xv.y, w1, acc[r]);
            acc[r] = fmaf(xv.z, w2, acc[r]);
            acc[r] = fmaf(xv.w, w3, acc[r]);
        }
    }

    float* gh = (float*)g_h4;
    #pragma unroll
    for (int r = 0; r < 32; r++) {
        int row = rowBase + rg * 32 + r;
        if (row < N_NODES)
            gh[(size_t)row * HIDDEN + c] = acc[r];
    }
}

// ---------------------------------------------------------------------------
// Scatter aggregation: one warp per (edge | self-loop).
// out[col] += dinv[row]*dinv[col] * h[row]   via global vector reductions.
// ---------------------------------------------------------------------------
__global__ void k_agg(const int* __restrict__ ei, int E,
                      float* __restrict__ out)
{
    const int lane   = threadIdx.x & 31;
    const int warp   = (blockIdx.x * blockDim.x + threadIdx.x) >> 5;
    const int nwarps = (gridDim.x * blockDim.x) >> 5;
    const int total  = E + N_NODES;

    for (int it = warp; it < total; it += nwarps) {
        int r, c; float w;
        if (it < E) {
            r = ei[it];
            c = ei[E + it];
            if ((unsigned)r >= N_NODES || (unsigned)c >= N_NODES) continue;
            w = g_dinv[r] * g_dinv[c];
        } else {
            r = c = it - E;
            float d = g_dinv[r];
            w = d * d;
        }
        float4 v = g_h4[(size_t)r * HID4 + lane];
        v.x *= w; v.y *= w; v.z *= w; v.w *= w;
        red_add_global_f4(out + (size_t)c * HIDDEN + 4 * lane, v);
    }
}

// ---------------------------------------------------------------------------
// BN pass 1: per-column sum / sumsq of raw aggregate (bias b cancels in BN).
// ---------------------------------------------------------------------------
__global__ void k_stats(const float* __restrict__ out)
{
    const int c   = threadIdx.x & (HIDDEN - 1);
    const int sub = threadIdx.x >> 7;                    // row-lane within block
    const int lanesPerBlock = blockDim.x >> 7;
    const int nRowLanes = gridDim.x * lanesPerBlock;
    const int rid = blockIdx.x * lanesPerBlock + sub;

    double s = 0.0, s2 = 0.0;
    for (int r = rid; r < N_NODES; r += nRowLanes) {
        float v = out[(size_t)r * HIDDEN + c];
        s  += v;
        s2 += (double)v * (double)v;
    }
    atomicAdd(&g_sum[c], s);
    atomicAdd(&g_sumsq[c], s2);
}

// ---------------------------------------------------------------------------
// BN pass 2a: fold mean/var/gamma/beta into per-column affine (scale, shift).
// ---------------------------------------------------------------------------
__global__ void k_finalize(const float* __restrict__ gamma,
                           const float* __restrict__ beta)
{
    int c = threadIdx.x;                                 // 128 threads
    double mean = g_sum[c]   / (double)N_NODES;
    double var  = g_sumsq[c] / (double)N_NODES - mean * mean;
    float inv = rsqrtf((float)var + BN_EPS);
    float sc  = gamma[c] * inv;
    ((float*)g_scale4)[c] = sc;
    ((float*)g_shift4)[c] = beta[c] - sc * (float)mean;
}

// ---------------------------------------------------------------------------
// BN pass 2b: out = out*scale + shift (vectorized float4).
// ---------------------------------------------------------------------------
__global__ void k_norm(float* __restrict__ out, int total)
{
    const int total4 = total >> 2;
    int i = blockIdx.x * blockDim.x + threadIdx.x;
    int stride = gridDim.x * blockDim.x;
    float4* o4 = (float4*)out;

    for (int idx = i; idx < total4; idx += stride) {
        int j = idx & (HID4 - 1);                        // column float4 group
        float4 v  = o4[idx];
        float4 sc = g_scale4[j];
        float4 sh = g_shift4[j];
        v.x = fmaf(v.x, sc.x, sh.x);
        v.y = fmaf(v.y, sc.y, sh.y);
        v.z = fmaf(v.z, sc.z, sh.z);
        v.w = fmaf(v.w, sc.w, sh.w);
        o4[idx] = v;
    }
}

// ---------------------------------------------------------------------------
extern "C" void kernel_launch(void* const* d_in, const int* in_sizes, int n_in,
                              void* d_out, int out_size)
{
    const float* x     = (const float*)d_in[0];
    const int*   ei    = (const int*)d_in[1];      // int32: JAX default config
    const float* W     = (const float*)d_in[2];
    // d_in[3] == b: cancels exactly inside BatchNorm -> unused
    const float* gamma = (const float*)d_in[4];
    const float* beta  = (const float*)d_in[5];
    float* out = (float*)d_out;

    const int E = in_sizes[1] / 2;

    k_init<<<2048, 256>>>(out, out_size);
    k_deg<<<(E + 255) / 256, 256>>>(ei + E, E);          // col = edge_index[1]
    k_dinv<<<(N_NODES + 255) / 256, 256>>>();
    k_gemm<<<(N_NODES + TILE_M - 1) / TILE_M, 256>>>(x, W);
    k_agg<<<2048, 256>>>(ei, E, out);
    k_stats<<<512, 256>>>(out);
    k_finalize<<<1, HIDDEN>>>(gamma, beta);
    k_norm<<<2048, 256>>>(out, out_size);
}

// round 7
// speedup vs baseline: 1.0830x; 1.0830x over previous
#include <cuda_runtime.h>

#define N_NODES 100000
#define HIDDEN  128
#define HID4    (HIDDEN / 4)
#define BN_EPS  1e-5f

// Scratch (device globals: no allocation allowed in kernel_launch).
// Declared as float4 so LDG.128/LDS.128 paths are guaranteed 16B-aligned.
__device__ float4 g_h4[(size_t)N_NODES * HID4];    // relu(x) @ W
__device__ int    g_deg[N_NODES];
__device__ float  g_dinv[N_NODES];
__device__ double g_sum[HIDDEN];
__device__ double g_sumsq[HIDDEN];
__device__ float4 g_scale4[HID4];
__device__ float4 g_shift4[HID4];

// Vector reduction into GLOBAL space. red.add.v4.f32 is only legal in
// .global — generic-space vector atomics trap. Explicitly convert the
// pointer and qualify the address space.
__device__ __forceinline__ void red_add_global_f4(float* addr, float4 v)
{
    unsigned long long gp = (unsigned long long)__cvta_generic_to_global(addr);
    asm volatile("red.global.add.v4.f32 [%0], {%1, %2, %3, %4};"
                 :: "l"(gp), "f"(v.x), "f"(v.y), "f"(v.z), "f"(v.w)
                 : "memory");
}

// ---------------------------------------------------------------------------
// Init: zero output (poisoned by harness), deg=1 (self loops), zero BN accum.
// ---------------------------------------------------------------------------
__global__ void k_init(float* __restrict__ out, int total)
{
    int i = blockIdx.x * blockDim.x + threadIdx.x;
    int stride = gridDim.x * blockDim.x;
    for (int idx = i; idx < total; idx += stride) out[idx] = 0.0f;
    for (int idx = i; idx < N_NODES; idx += stride) g_deg[idx] = 1;
    if (i < HIDDEN) { g_sum[i] = 0.0; g_sumsq[i] = 0.0; }
}

// ---------------------------------------------------------------------------
// Degree of target nodes (col), on top of the self-loop baseline of 1.
// edge_index is int32 (JAX default config downcasts int64 -> int32).
// ---------------------------------------------------------------------------
__global__ void k_deg(const int* __restrict__ col, int E)
{
    int i = blockIdx.x * blockDim.x + threadIdx.x;
    if (i < E) {
        int c = col[i];
        if (c >= 0 && c < N_NODES) atomicAdd(&g_deg[c], 1);
    }
}

__global__ void k_dinv()
{
    int i = blockIdx.x * blockDim.x + threadIdx.x;
    if (i < N_NODES) g_dinv[i] = rsqrtf((float)g_deg[i]);
}

// ---------------------------------------------------------------------------
// h = relu(x) @ W.   Register-tiled SGEMM.
// Block: 128 rows x 128 cols, 256 threads (16x16 thread grid), each thread
// an 8x8 micro-tile. K chunked at 32. x chunk stored TRANSPOSED in smem so
// both operand fetches are LDS.128. Per k-step: 4 LDS.128 -> 64 FMA
// (16 FMA per LDS, vs 4 in the previous L1-bound version).
// ---------------------------------------------------------------------------
#define BLOCK_M 128
#define KC      32

__global__ void __launch_bounds__(256) k_gemm(const float* __restrict__ x,
                                              const float* __restrict__ W)
{
    __shared__ __align__(16) float Ws[KC][HIDDEN];     // 16 KB  [k][col]
    __shared__ __align__(16) float Xs[KC][BLOCK_M];    // 16 KB  [k][row]

    const int tid = threadIdx.x;
    const int tx  = tid & 15;            // col group: cols tx*8 .. tx*8+7
    const int ty  = tid >> 4;            // row group: rows ty*8 .. ty*8+7
    const int rowBase = blockIdx.x * BLOCK_M;

    float acc[8][8];
    #pragma unroll
    for (int r = 0; r < 8; r++)
        #pragma unroll
        for (int c = 0; c < 8; c++) acc[r][c] = 0.f;

    for (int k0 = 0; k0 < HIDDEN; k0 += KC) {
        __syncthreads();                 // previous chunk fully consumed

        // W chunk: rows k0..k0+31 are 4096 contiguous floats. 4 float4/thread.
        {
            const float4* w4  = (const float4*)(W + k0 * HIDDEN);
            float4*       ws4 = (float4*)&Ws[0][0];
            #pragma unroll
            for (int i = 0; i < 4; i++)
                ws4[tid + 256 * i] = w4[tid + 256 * i];
        }
        // x chunk, transposed + ReLU: tile [128 rows][32 cols] -> Xs[k][row].
        // 1024 float4 loads, 4 per thread, fully coalesced on the global side.
        {
            #pragma unroll
            for (int i = 0; i < 4; i++) {
                int f   = tid + 256 * i;
                int row = f >> 3;                   // 0..127
                int q   = f & 7;                    // float4 index within 32 cols
                int grow = rowBase + row;
                float4 v = make_float4(0.f, 0.f, 0.f, 0.f);
                if (grow < N_NODES) {
                    v = *(const float4*)(x + (size_t)grow * HIDDEN + k0 + 4 * q);
                    v.x = fmaxf(v.x, 0.f); v.y = fmaxf(v.y, 0.f);
                    v.z = fmaxf(v.z, 0.f); v.w = fmaxf(v.w, 0.f);
                }
                Xs[4 * q + 0][row] = v.x;
                Xs[4 * q + 1][row] = v.y;
                Xs[4 * q + 2][row] = v.z;
                Xs[4 * q + 3][row] = v.w;
            }
        }
        __syncthreads();

        #pragma unroll
        for (int kk = 0; kk < KC; kk++) {
            float xr[8], wc[8];
            *(float4*)&xr[0] = *(const float4*)&Xs[kk][ty * 8];
            *(float4*)&xr[4] = *(const float4*)&Xs[kk][ty * 8 + 4];
            *(float4*)&wc[0] = *(const float4*)&Ws[kk][tx * 8];
            *(float4*)&wc[4] = *(const float4*)&Ws[kk][tx * 8 + 4];
            #pragma unroll
            for (int r = 0; r < 8; r++)
                #pragma unroll
                for (int c = 0; c < 8; c++)
                    acc[r][c] = fmaf(xr[r], wc[c], acc[r][c]);
        }
    }

    // Epilogue: two STG.128 per micro-row.
    float* gh = (float*)g_h4;
    #pragma unroll
    for (int r = 0; r < 8; r++) {
        int row = rowBase + ty * 8 + r;
        if (row < N_NODES) {
            float* dst = gh + (size_t)row * HIDDEN + tx * 8;
            *(float4*)dst       = *(float4*)&acc[r][0];
            *(float4*)(dst + 4) = *(float4*)&acc[r][4];
        }
    }
}

// ---------------------------------------------------------------------------
// Scatter aggregation: one warp per (edge | self-loop).
// out[col] += dinv[row]*dinv[col] * h[row]   via global vector reductions.
// ---------------------------------------------------------------------------
__global__ void k_agg(const int* __restrict__ ei, int E,
                      float* __restrict__ out)
{
    const int lane   = threadIdx.x & 31;
    const int warp   = (blockIdx.x * blockDim.x + threadIdx.x) >> 5;
    const int nwarps = (gridDim.x * blockDim.x) >> 5;
    const int total  = E + N_NODES;

    for (int it = warp; it < total; it += nwarps) {
        int r, c; float w;
        if (it < E) {
            r = ei[it];
            c = ei[E + it];
            if ((unsigned)r >= N_NODES || (unsigned)c >= N_NODES) continue;
            w = g_dinv[r] * g_dinv[c];
        } else {
            r = c = it - E;
            float d = g_dinv[r];
            w = d * d;
        }
        float4 v = g_h4[(size_t)r * HID4 + lane];
        v.x *= w; v.y *= w; v.z *= w; v.w *= w;
        red_add_global_f4(out + (size_t)c * HIDDEN + 4 * lane, v);
    }
}

// ---------------------------------------------------------------------------
// BN pass 1: per-column sum / sumsq of raw aggregate (bias b cancels in BN).
// ---------------------------------------------------------------------------
__global__ void k_stats(const float* __restrict__ out)
{
    const int c   = threadIdx.x & (HIDDEN - 1);
    const int sub = threadIdx.x >> 7;                    // row-lane within block
    const int lanesPerBlock = blockDim.x >> 7;
    const int nRowLanes = gridDim.x * lanesPerBlock;
    const int rid = blockIdx.x * lanesPerBlock + sub;

    double s = 0.0, s2 = 0.0;
    for (int r = rid; r < N_NODES; r += nRowLanes) {
        float v = out[(size_t)r * HIDDEN + c];
        s  += v;
        s2 += (double)v * (double)v;
    }
    atomicAdd(&g_sum[c], s);
    atomicAdd(&g_sumsq[c], s2);
}

// ---------------------------------------------------------------------------
// BN pass 2a: fold mean/var/gamma/beta into per-column affine (scale, shift).
// ---------------------------------------------------------------------------
__global__ void k_finalize(const float* __restrict__ gamma,
                           const float* __restrict__ beta)
{
    int c = threadIdx.x;                                 // 128 threads
    double mean = g_sum[c]   / (double)N_NODES;
    double var  = g_sumsq[c] / (double)N_NODES - mean * mean;
    float inv = rsqrtf((float)var + BN_EPS);
    float sc  = gamma[c] * inv;
    ((float*)g_scale4)[c] = sc;
    ((float*)g_shift4)[c] = beta[c] - sc * (float)mean;
}

// ---------------------------------------------------------------------------
// BN pass 2b: out = out*scale + shift (vectorized float4).
// ---------------------------------------------------------------------------
__global__ void k_norm(float* __restrict__ out, int total)
{
    const int total4 = total >> 2;
    int i = blockIdx.x * blockDim.x + threadIdx.x;
    int stride = gridDim.x * blockDim.x;
    float4* o4 = (float4*)out;

    for (int idx = i; idx < total4; idx += stride) {
        int j = idx & (HID4 - 1);                        // column float4 group
        float4 v  = o4[idx];
        float4 sc = g_scale4[j];
        float4 sh = g_shift4[j];
        v.x = fmaf(v.x, sc.x, sh.x);
        v.y = fmaf(v.y, sc.y, sh.y);
        v.z = fmaf(v.z, sc.z, sh.z);
        v.w = fmaf(v.w, sc.w, sh.w);
        o4[idx] = v;
    }
}

// ---------------------------------------------------------------------------
extern "C" void kernel_launch(void* const* d_in, const int* in_sizes, int n_in,
                              void* d_out, int out_size)
{
    const float* x     = (const float*)d_in[0];
    const int*   ei    = (const int*)d_in[1];      // int32: JAX default config
    const float* W     = (const float*)d_in[2];
    // d_in[3] == b: cancels exactly inside BatchNorm -> unused
    const float* gamma = (const float*)d_in[4];
    const float* beta  = (const float*)d_in[5];
    float* out = (float*)d_out;

    const int E = in_sizes[1] / 2;

    k_init<<<2048, 256>>>(out, out_size);
    k_deg<<<(E + 255) / 256, 256>>>(ei + E, E);          // col = edge_index[1]
    k_dinv<<<(N_NODES + 255) / 256, 256>>>();
    k_gemm<<<(N_NODES + BLOCK_M - 1) / BLOCK_M, 256>>>(x, W);
    k_agg<<<2048, 256>>>(ei, E, out);
    k_stats<<<512, 256>>>(out);
    k_finalize<<<1, HIDDEN>>>(gamma, beta);
    k_norm<<<2048, 256>>>(out, out_size);
}